// round 11
// baseline (speedup 1.0000x reference)
#include <cuda_runtime.h>
#include <cuda_fp16.h>

// ROIAlign via NHWC-fp16 pre-transpose, channel-half pipelined with PDL:
//   K1a: transpose ch[0:128)   (normal)
//   K2a: gather  half0         (normal; fires PDL trigger at entry)
//   K1b: transpose ch[128:256) (PDL secondary -> overlaps K2a; disjoint data)
//   K2b: gather  half1         (normal; stream order waits K1b + K2a)
// K1 is DRAM-bound, K2 is issue-bound: overlapping them reclaims the idle
// resource in each phase.
// spatial_scale=0.25, sampling_ratio=2, output (1000,256,7,7) fp32.

namespace {

constexpr int C_DIM = 256;
constexpr int H_DIM = 200;
constexpr int W_DIM = 304;
constexpr int S_DIM = H_DIM * W_DIM;        // 60800
constexpr int PH = 7, PW = 7;
constexpr int BINS = PH * PW;               // 49
constexpr float SCALE = 0.25f;
constexpr int CH_HALF = 128;                // channels per gather launch
constexpr int SM_PITCH = 132;               // floats per bin row (128 + pad)
constexpr int S_TILES = S_DIM / 32;         // 1900

__device__ __half g_nhwc[2ull * S_DIM * C_DIM];   // 62.3 MB scratch

__device__ __forceinline__ void axis_interp(float coord, int size,
                                            int& lo, int& hi,
                                            float& frac, bool& valid) {
    valid = (coord >= -1.0f) && (coord <= (float)size);
    float c = fmaxf(coord, 0.0f);
    int low = (int)c;
    if (low >= size - 1) { lo = size - 1; hi = size - 1; frac = 0.0f; }
    else                 { lo = low;      hi = low + 1;  frac = c - (float)low; }
}

// ---------------- K1: NCHW fp32 -> NHWC fp16 transpose (one channel half) --
// Tile: 64 channels x 32 spatial. Reads coalesced along spatial (128B),
// writes coalesced along channel (uint = 2 halves per lane, 128B rows).
__global__ __launch_bounds__(256)
void transpose_kernel(const float* __restrict__ feat, int half) {
    __shared__ __half tile[32][66];     // [spatial][channel], +2 pad

    int bid = blockIdx.x;
    int ct  = half * 2 + (bid & 1);     // channel tile (64 ch) within half
    int st  = (bid >> 1) % S_TILES;
    int n   = bid / (2 * S_TILES);
    int c0  = ct * 64;
    int s0  = st * 32;

    int lane = threadIdx.x & 31;
    int grp  = threadIdx.x >> 5;        // 0..7

    const float* src = feat + ((size_t)(n * C_DIM + c0)) * S_DIM + s0;
#pragma unroll
    for (int it = 0; it < 8; it++) {
        int c = it * 8 + grp;
        tile[lane][c] = __float2half(src[(size_t)c * S_DIM + lane]);
    }
    __syncthreads();

    const unsigned* tw = (const unsigned*)&tile[0][0];   // 33 words per row
    unsigned* dst = (unsigned*)(g_nhwc + ((size_t)n * S_DIM + s0) * C_DIM + c0);
#pragma unroll
    for (int it = 0; it < 4; it++) {
        int s = it * 8 + grp;
        dst[(size_t)s * (C_DIM / 2) + lane] = tw[s * 33 + lane];
    }
}

// ---------------- K2: gather (one channel half) ----------------
// Block = one box; 8 warps; warp w does bins s = w, w+8, ...
// Lane supplies channels half*128 + lane*4 via one uint2 (4 fp16):
// every bilinear corner is a dense 256B warp transaction. fp32 accumulation.
__global__ __launch_bounds__(256, 6)
void gather_kernel(const float* __restrict__ boxes,
                   float* __restrict__ out, int half) {
#if __CUDA_ARCH__ >= 900
    // PDL: as primary, release the next (attributed) kernel immediately —
    // the half-1 transpose shares no data with this launch.
    cudaTriggerProgrammaticLaunchCompletion();
#endif
    __shared__ float sm[BINS * SM_PITCH];   // 25.9 KB

    int r    = blockIdx.x;
    int tid  = threadIdx.x;
    int lane = tid & 31;
    int w    = tid >> 5;

    const float* bx = boxes + (size_t)r * 5;
    int   nb = (int)__ldg(bx + 0);
    float x1 = __ldg(bx + 1) * SCALE;
    float y1 = __ldg(bx + 2) * SCALE;
    float x2 = __ldg(bx + 3) * SCALE;
    float y2 = __ldg(bx + 4) * SCALE;
    float bin_w = fmaxf(x2 - x1, 1.0f) * (1.0f / PW);
    float bin_h = fmaxf(y2 - y1, 1.0f) * (1.0f / PH);

    const __half* base = g_nhwc + (size_t)nb * S_DIM * C_DIM
                       + half * CH_HALF + (lane << 2);

    for (int s = w; s < BINS; s += 8) {
        int ph = s / PW, pw = s % PW;

        // 4 candidate rows (2 samples x lo/hi) and 4 candidate cols with
        // axis validity folded into the weights (all lane-uniform).
        int   ro[4], xo[4];
        float wy[4], wx[4];
#pragma unroll
        for (int i = 0; i < 2; i++) {
            float yc = y1 + ((float)ph + ((float)i + 0.5f) * 0.5f) * bin_h;
            float xc = x1 + ((float)pw + ((float)i + 0.5f) * 0.5f) * bin_w;
            int yl, yh, xl, xh; float fy, fx; bool vy, vx;
            axis_interp(yc, H_DIM, yl, yh, fy, vy);
            axis_interp(xc, W_DIM, xl, xh, fx, vx);
            ro[2 * i]     = (yl * W_DIM) * C_DIM;
            ro[2 * i + 1] = (yh * W_DIM) * C_DIM;
            wy[2 * i]     = vy ? (1.0f - fy) : 0.0f;
            wy[2 * i + 1] = vy ? fy          : 0.0f;
            xo[2 * i]     = xl * C_DIM;
            xo[2 * i + 1] = xh * C_DIM;
            wx[2 * i]     = vx ? (1.0f - fx) : 0.0f;
            wx[2 * i + 1] = vx ? fx          : 0.0f;
        }

        float a0 = 0.f, a1 = 0.f, a2 = 0.f, a3 = 0.f;

        // Two batches of 8 loads; each batch fully issued before any
        // consumption -> MLP >= 8 under the register cap.
#pragma unroll
        for (int batch = 0; batch < 2; batch++) {
            uint2 v[8];
#pragma unroll
            for (int j = 0; j < 8; j++) {
                int a  = batch * 2 + (j >> 2);
                int b2 = j & 3;
                v[j] = __ldg((const uint2*)(base + ro[a] + xo[b2]));
            }
#pragma unroll
            for (int j = 0; j < 8; j++) {
                int a  = batch * 2 + (j >> 2);
                int b2 = j & 3;
                float wgt = wy[a] * wx[b2];
                float2 f0 = __half22float2(*(const __half2*)&v[j].x);
                float2 f1 = __half22float2(*(const __half2*)&v[j].y);
                a0 += wgt * f0.x;  a1 += wgt * f0.y;
                a2 += wgt * f1.x;  a3 += wgt * f1.y;
            }
        }

        // Mean over the 2x2 sample grid; 16B-aligned conflict-free STS.
        ((float4*)(sm + s * SM_PITCH))[lane] =
            make_float4(a0 * 0.25f, a1 * 0.25f, a2 * 0.25f, a3 * 0.25f);
    }
    __syncthreads();

    // Coalesced epilogue: this launch's 128 channels x 49 bins are contiguous
    // in the (R, C, 7, 7) output.
    float* o = out + (size_t)r * (C_DIM * BINS) + (size_t)half * (CH_HALF * BINS);
    for (int q = tid; q < CH_HALF * BINS; q += 256) {
        int c  = q / BINS;
        int sb = q - c * BINS;
        o[q] = sm[sb * SM_PITCH + c];
    }
}

} // namespace

extern "C" void kernel_launch(void* const* d_in, const int* in_sizes, int n_in,
                              void* d_out, int out_size) {
    const float* features = (const float*)d_in[0];
    const float* boxes    = (const float*)d_in[1];
    float*       out      = (float*)d_out;

    int R = in_sizes[1] / 5;                          // 1000 boxes
    int tblocks_half = 2 * 2 * S_TILES;               // 7600 per channel half

    // K1a: transpose channels [0,128)   (normal launch)
    transpose_kernel<<<tblocks_half, 256>>>(features, 0);

    // K2a: gather half 0 (normal launch; fires PDL trigger at entry)
    gather_kernel<<<R, 256>>>(boxes, out, 0);

    // K1b: transpose channels [128,256) as PDL secondary -> starts as soon as
    // K2a's blocks have triggered, overlapping the issue-bound gather with
    // this DRAM-bound transpose. Touches only disjoint scratch.
    {
        cudaLaunchAttribute attr[1];
        attr[0].id = cudaLaunchAttributeProgrammaticStreamSerialization;
        attr[0].val.programmaticStreamSerializationAllowed = 1;
        cudaLaunchConfig_t cfg = {};
        cfg.gridDim  = dim3(tblocks_half);
        cfg.blockDim = dim3(256);
        cfg.dynamicSmemBytes = 0;
        cfg.stream = 0;
        cfg.attrs = attr;
        cfg.numAttrs = 1;
        cudaLaunchKernelEx(&cfg, transpose_kernel, features, 1);
    }

    // K2b: gather half 1 (normal launch; stream order waits K1b and K2a)
    gather_kernel<<<R, 256>>>(boxes, out, 1);
}

// round 13
// speedup vs baseline: 1.1616x; 1.1616x over previous
#include <cuda_runtime.h>
#include <cuda_fp16.h>

// ROIAlign via NHWC-fp16 pre-transpose (serial two-kernel):
//   K1: features (2,256,200,304) fp32 NCHW -> g_nhwc (2, 200*304, 256) fp16
//   K2: gather, block = one box; lane = 8 contiguous fp16 channels (uint4)
//       -> full 256-channel corner in ONE 512B warp transaction; coord math
//       computed once per (box,bin). fp32 accumulation. Staging buffer is
//       DYNAMIC smem (51 KB): pitch 260 >= 256 channels (R11's pitch-250
//       cross-row overwrite fixed).
// spatial_scale=0.25, sampling_ratio=2, output (1000,256,7,7) fp32.

namespace {

constexpr int C_DIM = 256;
constexpr int H_DIM = 200;
constexpr int W_DIM = 304;
constexpr int S_DIM = H_DIM * W_DIM;        // 60800
constexpr int PH = 7, PW = 7;
constexpr int BINS = PH * PW;               // 49
constexpr float SCALE = 0.25f;
constexpr int S_TILES = S_DIM / 32;         // 1900
constexpr int SM_PITCH = 260;               // floats per bin row (>=256 + pad)
constexpr int SMEM_BYTES = BINS * SM_PITCH * 4;   // 50960 B (dynamic)

__device__ __half g_nhwc[2ull * S_DIM * C_DIM];   // 62.3 MB scratch

__device__ __forceinline__ void axis_interp(float coord, int size,
                                            int& lo, int& hi,
                                            float& frac, bool& valid) {
    valid = (coord >= -1.0f) && (coord <= (float)size);
    float c = fmaxf(coord, 0.0f);
    int low = (int)c;
    if (low >= size - 1) { lo = size - 1; hi = size - 1; frac = 0.0f; }
    else                 { lo = low;      hi = low + 1;  frac = c - (float)low; }
}

// ---------------- K1: NCHW fp32 -> NHWC fp16 transpose ----------------
// Tile: 64 channels x 32 spatial. Reads coalesced along spatial (128B),
// writes coalesced along channel (uint = 2 halves per lane, 128B rows).
__global__ __launch_bounds__(256)
void transpose_kernel(const float* __restrict__ feat) {
    __shared__ __half tile[32][66];     // [spatial][channel], +2 pad

    int bid = blockIdx.x;
    int ct  = bid & 3;                  // 4 channel tiles of 64
    int st  = (bid >> 2) % S_TILES;
    int n   = bid / (4 * S_TILES);
    int c0  = ct * 64;
    int s0  = st * 32;

    int lane = threadIdx.x & 31;
    int grp  = threadIdx.x >> 5;        // 0..7

    const float* src = feat + ((size_t)(n * C_DIM + c0)) * S_DIM + s0;
#pragma unroll
    for (int it = 0; it < 8; it++) {
        int c = it * 8 + grp;
        tile[lane][c] = __float2half(src[(size_t)c * S_DIM + lane]);
    }
    __syncthreads();

    const unsigned* tw = (const unsigned*)&tile[0][0];   // 33 words per row
    unsigned* dst = (unsigned*)(g_nhwc + ((size_t)n * S_DIM + s0) * C_DIM + c0);
#pragma unroll
    for (int it = 0; it < 4; it++) {
        int s = it * 8 + grp;
        dst[(size_t)s * (C_DIM / 2) + lane] = tw[s * 33 + lane];
    }
}

// ---------------- K2: gather ----------------
// Block = one box; 8 warps; warp w does bins s = w, w+8, ...
// Lane supplies channels lane*8 .. lane*8+7 via one uint4 (8 fp16).
__global__ __launch_bounds__(256, 4)
void gather_kernel(const float* __restrict__ boxes,
                   float* __restrict__ out) {
    extern __shared__ float sm[];           // BINS * SM_PITCH floats (51 KB)

    int r    = blockIdx.x;
    int tid  = threadIdx.x;
    int lane = tid & 31;
    int w    = tid >> 5;

    const float* bx = boxes + (size_t)r * 5;
    int   nb = (int)__ldg(bx + 0);
    float x1 = __ldg(bx + 1) * SCALE;
    float y1 = __ldg(bx + 2) * SCALE;
    float x2 = __ldg(bx + 3) * SCALE;
    float y2 = __ldg(bx + 4) * SCALE;
    float bin_w = fmaxf(x2 - x1, 1.0f) * (1.0f / PW);
    float bin_h = fmaxf(y2 - y1, 1.0f) * (1.0f / PH);

    const __half* base = g_nhwc + (size_t)nb * S_DIM * C_DIM + (lane << 3);

    for (int s = w; s < BINS; s += 8) {
        int ph = s / PW, pw = s % PW;

        // 4 candidate rows (2 samples x lo/hi) and 4 candidate cols with
        // axis validity folded into the weights; 0.25 sample-mean folded
        // into wy. All lane-uniform.
        int   ro[4], xo[4];
        float wy[4], wx[4];
#pragma unroll
        for (int i = 0; i < 2; i++) {
            float yc = y1 + ((float)ph + ((float)i + 0.5f) * 0.5f) * bin_h;
            float xc = x1 + ((float)pw + ((float)i + 0.5f) * 0.5f) * bin_w;
            int yl, yh, xl, xh; float fy, fx; bool vy, vx;
            axis_interp(yc, H_DIM, yl, yh, fy, vy);
            axis_interp(xc, W_DIM, xl, xh, fx, vx);
            ro[2 * i]     = (yl * W_DIM) * C_DIM;
            ro[2 * i + 1] = (yh * W_DIM) * C_DIM;
            wy[2 * i]     = vy ? (1.0f - fy) * 0.25f : 0.0f;
            wy[2 * i + 1] = vy ? fy * 0.25f          : 0.0f;
            xo[2 * i]     = xl * C_DIM;
            xo[2 * i + 1] = xh * C_DIM;
            wx[2 * i]     = vx ? (1.0f - fx) : 0.0f;
            wx[2 * i + 1] = vx ? fx          : 0.0f;
        }

        float a0 = 0.f, a1 = 0.f, a2 = 0.f, a3 = 0.f;
        float a4 = 0.f, a5 = 0.f, a6 = 0.f, a7 = 0.f;

        // One row per batch: 4 independent uint4 loads issued back-to-back,
        // consumption overlaps the next row's loads (ILP across rows).
#pragma unroll
        for (int a = 0; a < 4; a++) {
            const __half* rp = base + ro[a];
            uint4 v[4];
#pragma unroll
            for (int b2 = 0; b2 < 4; b2++)
                v[b2] = __ldg((const uint4*)(rp + xo[b2]));
#pragma unroll
            for (int b2 = 0; b2 < 4; b2++) {
                float wgt = wy[a] * wx[b2];
                float2 f0 = __half22float2(*(const __half2*)&v[b2].x);
                float2 f1 = __half22float2(*(const __half2*)&v[b2].y);
                float2 f2 = __half22float2(*(const __half2*)&v[b2].z);
                float2 f3 = __half22float2(*(const __half2*)&v[b2].w);
                a0 += wgt * f0.x;  a1 += wgt * f0.y;
                a2 += wgt * f1.x;  a3 += wgt * f1.y;
                a4 += wgt * f2.x;  a5 += wgt * f2.y;
                a6 += wgt * f3.x;  a7 += wgt * f3.y;
            }
        }

        // Stage channels lane*8 .. lane*8+7 (max float offset 255 < 260 ✓)
        // as 4x float2 (8B aligned: pitch*4 = 1040 B, lane*32 B).
        float2* row = (float2*)(sm + s * SM_PITCH) + (lane << 2);
        row[0] = make_float2(a0, a1);
        row[1] = make_float2(a2, a3);
        row[2] = make_float2(a4, a5);
        row[3] = make_float2(a6, a7);
    }
    __syncthreads();

    // Coalesced epilogue: box's (256 ch x 49 bins) block is contiguous in
    // the (R, C, 7, 7) output.
    float* o = out + (size_t)r * (C_DIM * BINS);
    for (int q = tid; q < C_DIM * BINS; q += 256) {
        int c  = q / BINS;
        int sb = q - c * BINS;
        o[q] = sm[sb * SM_PITCH + c];
    }
}

} // namespace

extern "C" void kernel_launch(void* const* d_in, const int* in_sizes, int n_in,
                              void* d_out, int out_size) {
    const float* features = (const float*)d_in[0];
    const float* boxes    = (const float*)d_in[1];
    float*       out      = (float*)d_out;

    int R = in_sizes[1] / 5;                          // 1000 boxes

    // Allow >48KB dynamic smem for the gather (idempotent, capture-safe).
    cudaFuncSetAttribute(gather_kernel,
                         cudaFuncAttributeMaxDynamicSharedMemorySize,
                         SMEM_BYTES);

    int tblocks = 2 * 4 * S_TILES;                    // 15200
    transpose_kernel<<<tblocks, 256>>>(features);
    gather_kernel<<<R, 256, SMEM_BYTES>>>(boxes, out);
}